// round 1
// baseline (speedup 1.0000x reference)
#include <cuda_runtime.h>

#define Bc 2
#define Tt 2048
#define Cc 2048
#define NH 16
#define KVH 4
#define HD 128
#define QKV_OUT 3072
#define MROWS 4096   // B*T

#define BQ 64
#define BKV 64
#define SP 65        // padded S row

// ---------------- scratch (static device arrays; no allocation allowed) ------
__device__ float g_qkv[(size_t)MROWS * QKV_OUT];           // 50 MB
__device__ float g_q[(size_t)Bc * NH * Tt * HD];           // 33.5 MB
__device__ float g_k[(size_t)Bc * KVH * Tt * HD];          // 8.4 MB
__device__ float g_v[(size_t)Bc * KVH * Tt * HD];          // 8.4 MB
__device__ float g_y[(size_t)MROWS * Cc];                  // 33.5 MB

// ---------------- SGEMM: C[M,N] = A[M,K] * B[N,K]^T (both K-contiguous) ------
__global__ void __launch_bounds__(256) sgemm_nt(const float* __restrict__ A,
                                                const float* __restrict__ B,
                                                float* __restrict__ C,
                                                int M, int N, int K) {
    const int BM = 128, BN = 128, BK = 16;
    __shared__ float As[BK][BM];
    __shared__ float Bs[BK][BN];
    int tid = threadIdx.x;
    int ty = tid >> 4, tx = tid & 15;
    int m0 = blockIdx.y * BM, n0 = blockIdx.x * BN;

    float acc[8][8];
#pragma unroll
    for (int i = 0; i < 8; i++)
#pragma unroll
        for (int j = 0; j < 8; j++) acc[i][j] = 0.f;

    for (int kk = 0; kk < K; kk += BK) {
#pragma unroll
        for (int it = 0; it < 2; it++) {
            int id = tid + it * 256;       // 0..511
            int row = id >> 2;             // 0..127
            int k4 = id & 3;               // 0..3
            float4 va = *reinterpret_cast<const float4*>(&A[(size_t)(m0 + row) * K + kk + k4 * 4]);
            As[k4 * 4 + 0][row] = va.x; As[k4 * 4 + 1][row] = va.y;
            As[k4 * 4 + 2][row] = va.z; As[k4 * 4 + 3][row] = va.w;
            float4 vb = *reinterpret_cast<const float4*>(&B[(size_t)(n0 + row) * K + kk + k4 * 4]);
            Bs[k4 * 4 + 0][row] = vb.x; Bs[k4 * 4 + 1][row] = vb.y;
            Bs[k4 * 4 + 2][row] = vb.z; Bs[k4 * 4 + 3][row] = vb.w;
        }
        __syncthreads();
#pragma unroll
        for (int k = 0; k < BK; k++) {
            float a[8], b[8];
            *reinterpret_cast<float4*>(&a[0]) = *reinterpret_cast<const float4*>(&As[k][ty * 8]);
            *reinterpret_cast<float4*>(&a[4]) = *reinterpret_cast<const float4*>(&As[k][ty * 8 + 4]);
            *reinterpret_cast<float4*>(&b[0]) = *reinterpret_cast<const float4*>(&Bs[k][tx * 8]);
            *reinterpret_cast<float4*>(&b[4]) = *reinterpret_cast<const float4*>(&Bs[k][tx * 8 + 4]);
#pragma unroll
            for (int i = 0; i < 8; i++)
#pragma unroll
                for (int j = 0; j < 8; j++) acc[i][j] += a[i] * b[j];
        }
        __syncthreads();
    }
#pragma unroll
    for (int i = 0; i < 8; i++) {
        int m = m0 + ty * 8 + i;
        float4* cp = reinterpret_cast<float4*>(&C[(size_t)m * N + n0 + tx * 8]);
        cp[0] = make_float4(acc[i][0], acc[i][1], acc[i][2], acc[i][3]);
        cp[1] = make_float4(acc[i][4], acc[i][5], acc[i][6], acc[i][7]);
    }
}

// ---------------- RoPE + RMSNorm + scatter to head-major layouts -------------
// block: (b*T+t, slot) slot 0..15=q heads, 16..19=k heads, 20..23=v heads; 128 thr
__global__ void __launch_bounds__(128) rope_norm_kernel(
    const float* __restrict__ qkv, const float* __restrict__ qw,
    const float* __restrict__ kw, const float* __restrict__ cosf,
    const float* __restrict__ sinf,
    float* __restrict__ Q, float* __restrict__ K, float* __restrict__ V) {
    int bt = blockIdx.x;
    int slot = blockIdx.y;
    int d = threadIdx.x;
    int b = bt / Tt, t = bt % Tt;
    float v = qkv[(size_t)bt * QKV_OUT + slot * HD + d];
    if (slot >= 20) {                       // V: plain copy (uniform per block)
        int kh = slot - 20;
        V[(((size_t)(b * KVH + kh)) * Tt + t) * HD + d] = v;
        return;
    }
    // RoPE (even/odd interleaved pairs; partner is adjacent lane)
    float partner = __shfl_xor_sync(0xffffffffu, v, 1);
    int i = d >> 1;
    float c = cosf[t * (HD / 2) + i];
    float s = sinf[t * (HD / 2) + i];
    float o = ((d & 1) == 0) ? (v * c - partner * s) : (partner * s + v * c);
    // RMSNorm over the 128 roped values
    __shared__ float red[4];
    float ss = o * o;
#pragma unroll
    for (int off = 16; off > 0; off >>= 1) ss += __shfl_xor_sync(0xffffffffu, ss, off);
    if ((d & 31) == 0) red[d >> 5] = ss;
    __syncthreads();
    float tot = red[0] + red[1] + red[2] + red[3];
    float r = rsqrtf(tot * (1.0f / HD) + 1e-6f);
    if (slot < 16) {
        Q[(((size_t)(b * NH + slot)) * Tt + t) * HD + d] = qw[d] * o * r;
    } else {
        int kh = slot - 16;
        K[(((size_t)(b * KVH + kh)) * Tt + t) * HD + d] = kw[d] * o * r;
    }
}

// ---------------- causal flash attention (fp32, 64x64 tiles) -----------------
// grid: (T/BQ, NH, B), 256 threads
__global__ void __launch_bounds__(256) attn_kernel(
    const float* __restrict__ Q, const float* __restrict__ K,
    const float* __restrict__ V, float* __restrict__ Y) {
    extern __shared__ float sm[];
    float* Qs = sm;                     // [HD][BQ] transposed
    float* Ks = Qs + HD * BQ;           // [HD][BKV] transposed
    float* Vs = Ks + HD * BKV;          // [BKV][HD]
    float* S  = Vs + BKV * HD;          // [BQ][SP]
    float* m_s = S + BQ * SP;           // [BQ]
    float* l_s = m_s + BQ;              // [BQ]
    float* rsc = l_s + BQ;              // [BQ]

    int tid = threadIdx.x;
    int qt = blockIdx.x;
    int h = blockIdx.y;
    int b = blockIdx.z;
    int kvh = h / (NH / KVH);

    const float* Qg = Q + (((size_t)(b * NH + h)) * Tt + qt * BQ) * HD;
    const float* Kg = K + ((size_t)(b * KVH + kvh)) * Tt * HD;
    const float* Vg = V + ((size_t)(b * KVH + kvh)) * Tt * HD;
    const float scale = 0.08838834764831845f;  // 1/sqrt(128)

    // load Q tile transposed, pre-scaled
#pragma unroll
    for (int it = 0; it < 8; it++) {
        int id = tid + it * 256;       // 0..2047
        int row = id >> 5;             // 0..63
        int k4 = id & 31;
        float4 v4 = *reinterpret_cast<const float4*>(&Qg[row * HD + k4 * 4]);
        Qs[(k4 * 4 + 0) * BQ + row] = v4.x * scale;
        Qs[(k4 * 4 + 1) * BQ + row] = v4.y * scale;
        Qs[(k4 * 4 + 2) * BQ + row] = v4.z * scale;
        Qs[(k4 * 4 + 3) * BQ + row] = v4.w * scale;
    }
    if (tid < BQ) { m_s[tid] = -3.0e38f; l_s[tid] = 0.f; }

    // S-phase mapping: 4x4 per thread
    int gi = tid >> 4;     // i0 = gi*4
    int gj = tid & 15;     // j0 = gj*4
    // PV mapping: 4 rows x 8 cols per thread
    int ii = tid >> 4;     // rows ii*4..+3
    int di = tid & 15;     // d0 = di*8

    float oacc[4][8];
#pragma unroll
    for (int i = 0; i < 4; i++)
#pragma unroll
        for (int j = 0; j < 8; j++) oacc[i][j] = 0.f;

    int ntiles = qt + 1;
    for (int kt = 0; kt < ntiles; kt++) {
        int kv0 = kt * BKV;
        __syncthreads();   // previous PV done before overwriting Ks/Vs
        // load K (transposed) and V tiles
#pragma unroll
        for (int it = 0; it < 8; it++) {
            int id = tid + it * 256;
            int row = id >> 5;
            int k4 = id & 31;
            float4 v4 = *reinterpret_cast<const float4*>(&Kg[(size_t)(kv0 + row) * HD + k4 * 4]);
            Ks[(k4 * 4 + 0) * BKV + row] = v4.x;
            Ks[(k4 * 4 + 1) * BKV + row] = v4.y;
            Ks[(k4 * 4 + 2) * BKV + row] = v4.z;
            Ks[(k4 * 4 + 3) * BKV + row] = v4.w;
            float4 w4 = *reinterpret_cast<const float4*>(&Vg[(size_t)(kv0 + row) * HD + k4 * 4]);
            *reinterpret_cast<float4*>(&Vs[row * HD + k4 * 4]) = w4;
        }
        __syncthreads();
        // S = Q * K^T (64x64), 4x4 per thread
        float sacc[4][4];
#pragma unroll
        for (int i = 0; i < 4; i++)
#pragma unroll
            for (int j = 0; j < 4; j++) sacc[i][j] = 0.f;
#pragma unroll 4
        for (int k = 0; k < HD; k++) {
            float4 qa = *reinterpret_cast<const float4*>(&Qs[k * BQ + gi * 4]);
            float4 kb = *reinterpret_cast<const float4*>(&Ks[k * BKV + gj * 4]);
            float qv[4] = {qa.x, qa.y, qa.z, qa.w};
            float kv[4] = {kb.x, kb.y, kb.z, kb.w};
#pragma unroll
            for (int i = 0; i < 4; i++)
#pragma unroll
                for (int j = 0; j < 4; j++) sacc[i][j] += qv[i] * kv[j];
        }
#pragma unroll
        for (int i = 0; i < 4; i++)
#pragma unroll
            for (int j = 0; j < 4; j++)
                S[(gi * 4 + i) * SP + gj * 4 + j] = sacc[i][j];
        __syncthreads();
        // online softmax stats: thread i owns row i (causal mask applied here)
        if (tid < BQ) {
            int irow = tid;
            int qglob = qt * BQ + irow;
            int jmax = qglob - kv0 + 1;
            if (jmax > BKV) jmax = BKV;
            float mold = m_s[irow];
            float mx = mold;
            for (int j = 0; j < jmax; j++) mx = fmaxf(mx, S[irow * SP + j]);
            float sum = 0.f;
            for (int j = 0; j < jmax; j++) {
                float p = __expf(S[irow * SP + j] - mx);
                S[irow * SP + j] = p;
                sum += p;
            }
            for (int j = jmax; j < BKV; j++) S[irow * SP + j] = 0.f;
            float r = __expf(mold - mx);
            l_s[irow] = l_s[irow] * r + sum;
            m_s[irow] = mx;
            rsc[irow] = r;
        }
        __syncthreads();
        // rescale old accumulator and add P*V
        float r0 = rsc[ii * 4 + 0], r1 = rsc[ii * 4 + 1];
        float r2 = rsc[ii * 4 + 2], r3 = rsc[ii * 4 + 3];
#pragma unroll
        for (int j = 0; j < 8; j++) {
            oacc[0][j] *= r0; oacc[1][j] *= r1; oacc[2][j] *= r2; oacc[3][j] *= r3;
        }
#pragma unroll 2
        for (int j = 0; j < BKV; j++) {
            float p0 = S[(ii * 4 + 0) * SP + j];
            float p1 = S[(ii * 4 + 1) * SP + j];
            float p2 = S[(ii * 4 + 2) * SP + j];
            float p3 = S[(ii * 4 + 3) * SP + j];
            float4 v0 = *reinterpret_cast<const float4*>(&Vs[j * HD + di * 8]);
            float4 v1 = *reinterpret_cast<const float4*>(&Vs[j * HD + di * 8 + 4]);
            float vv[8] = {v0.x, v0.y, v0.z, v0.w, v1.x, v1.y, v1.z, v1.w};
#pragma unroll
            for (int d = 0; d < 8; d++) {
                oacc[0][d] += p0 * vv[d];
                oacc[1][d] += p1 * vv[d];
                oacc[2][d] += p2 * vv[d];
                oacc[3][d] += p3 * vv[d];
            }
        }
    }
    // epilogue: normalize and write y in [b, t, h*HD + d] layout for proj GEMM
#pragma unroll
    for (int r = 0; r < 4; r++) {
        int row = ii * 4 + r;
        float invl = 1.0f / l_s[row];
        size_t base = ((size_t)(b * Tt) + qt * BQ + row) * Cc + h * HD + di * 8;
        float4 o0 = make_float4(oacc[r][0] * invl, oacc[r][1] * invl,
                                oacc[r][2] * invl, oacc[r][3] * invl);
        float4 o1 = make_float4(oacc[r][4] * invl, oacc[r][5] * invl,
                                oacc[r][6] * invl, oacc[r][7] * invl);
        *reinterpret_cast<float4*>(&Y[base]) = o0;
        *reinterpret_cast<float4*>(&Y[base + 4]) = o1;
    }
}

// ---------------- host launcher ---------------------------------------------
extern "C" void kernel_launch(void* const* d_in, const int* in_sizes, int n_in,
                              void* d_out, int out_size) {
    const float* x      = (const float*)d_in[0];
    const float* w_qkv  = (const float*)d_in[1];
    const float* w_proj = (const float*)d_in[2];
    const float* qw     = (const float*)d_in[3];
    const float* kw     = (const float*)d_in[4];
    const float* fc     = (const float*)d_in[5];
    const float* fs     = (const float*)d_in[6];
    float* out = (float*)d_out;

    float *qkv, *Q, *K, *V, *Y;
    cudaGetSymbolAddress((void**)&qkv, g_qkv);
    cudaGetSymbolAddress((void**)&Q, g_q);
    cudaGetSymbolAddress((void**)&K, g_k);
    cudaGetSymbolAddress((void**)&V, g_v);
    cudaGetSymbolAddress((void**)&Y, g_y);

    const int attn_smem = (HD * BQ + HD * BKV + BKV * HD + BQ * SP + 3 * BQ) * 4;
    cudaFuncSetAttribute(attn_kernel, cudaFuncAttributeMaxDynamicSharedMemorySize,
                         attn_smem);

    // 1) QKV GEMM
    sgemm_nt<<<dim3(QKV_OUT / 128, MROWS / 128), 256>>>(x, w_qkv, qkv, MROWS, QKV_OUT, Cc);
    // 2) RoPE + RMSNorm + head scatter
    rope_norm_kernel<<<dim3(MROWS, NH + 2 * KVH), 128>>>(qkv, qw, kw, fc, fs, Q, K, V);
    // 3) causal flash attention
    attn_kernel<<<dim3(Tt / BQ, NH, Bc), 256, attn_smem>>>(Q, K, V, Y);
    // 4) output projection
    sgemm_nt<<<dim3(Cc / 128, MROWS / 128), 256>>>(Y, w_proj, out, MROWS, Cc, Cc);
}

// round 5
// speedup vs baseline: 2.3025x; 2.3025x over previous
#include <cuda_runtime.h>
#include <cuda_bf16.h>
#include <cstdint>

#define Bc 2
#define Tt 2048
#define Cc 2048
#define NH 16
#define KVH 4
#define HD 128
#define QKV_OUT 3072
#define MROWS 4096   // B*T

#define BQ 64
#define BKV 64

// ---------------- scratch ----------------------------------------------------
__device__ float g_qkv[(size_t)MROWS * QKV_OUT];
__device__ float g_q[(size_t)Bc * NH * Tt * HD];
__device__ float g_k[(size_t)Bc * KVH * Tt * HD];
__device__ float g_v[(size_t)Bc * KVH * Tt * HD];
__device__ float g_y[(size_t)MROWS * Cc];

// ---------------- helpers ----------------------------------------------------
// bf16 mma m16n8k16: D = A*B + D (row.col)
__device__ __forceinline__ void mma_bf16(float* d, const uint32_t* a, const uint32_t* b) {
    asm volatile(
        "mma.sync.aligned.m16n8k16.row.col.f32.bf16.bf16.f32 "
        "{%0,%1,%2,%3}, {%4,%5,%6,%7}, {%8,%9}, {%0,%1,%2,%3};"
        : "+f"(d[0]), "+f"(d[1]), "+f"(d[2]), "+f"(d[3])
        : "r"(a[0]), "r"(a[1]), "r"(a[2]), "r"(a[3]), "r"(b[0]), "r"(b[1]));
}

// split (x,y) into packed-bf16 hi word and lo (residual) word; x in low half
__device__ __forceinline__ void split2(float x, float y, uint32_t& hi, uint32_t& lo) {
    __nv_bfloat16 hx = __float2bfloat16(x);
    __nv_bfloat16 hy = __float2bfloat16(y);
    __nv_bfloat16 lx = __float2bfloat16(x - __bfloat162float(hx));
    __nv_bfloat16 ly = __float2bfloat16(y - __bfloat162float(hy));
    hi = (uint32_t)__bfloat16_as_ushort(hx) | ((uint32_t)__bfloat16_as_ushort(hy) << 16);
    lo = (uint32_t)__bfloat16_as_ushort(lx) | ((uint32_t)__bfloat16_as_ushort(ly) << 16);
}

// ======================= bf16x3 GEMM =========================================
// C[M,N] = A[M,K] * B[N,K]^T.  CTA 128x128, BK=32, 8 warps @ 64x32, dbl-buffer.
// smem word layout per stage: AHI[128*20] ALO BHI BLO (stride 20 words = 40 bf16)
#define GW 20                 // words per smem row
#define GOP (128 * GW)        // words per operand (2560)
#define GSTGW (4 * GOP)       // words per stage (10240)

__global__ void __launch_bounds__(256, 1) gemm_bf3(const float* __restrict__ A,
                                                   const float* __restrict__ B,
                                                   float* __restrict__ C,
                                                   int K, int N) {
    extern __shared__ __align__(16) uint32_t sw[];
    const int tid = threadIdx.x;
    const int warp = tid >> 5, lane = tid & 31;
    const int gid = lane >> 2, tg = lane & 3;
    const int warpm = warp >> 2, warpn = warp & 3;
    const int m0 = blockIdx.y * 128, n0 = blockIdx.x * 128;
    const int NIT = K / 32;
    const int lrow = tid >> 3, lc = tid & 7;   // load mapping: 32 rows/iter? no: see below

    float acc[4][4][4];
#pragma unroll
    for (int i = 0; i < 4; i++)
#pragma unroll
        for (int j = 0; j < 4; j++)
#pragma unroll
            for (int r = 0; r < 4; r++) acc[i][j][r] = 0.f;

    float4 pa[4], pb[4];

    auto load_regs = [&](int kk) {
        const float* Ag = A + (size_t)m0 * K + kk;
        const float* Bg = B + (size_t)n0 * K + kk;
#pragma unroll
        for (int i = 0; i < 4; i++) {
            int row = lrow + i * 32;
            pa[i] = *reinterpret_cast<const float4*>(&Ag[(size_t)row * K + lc * 4]);
            pb[i] = *reinterpret_cast<const float4*>(&Bg[(size_t)row * K + lc * 4]);
        }
    };
    auto store_stage = [&](uint32_t* sb) {
#pragma unroll
        for (int i = 0; i < 4; i++) {
            int row = lrow + i * 32;
            int off = row * GW + lc * 2;
            uint32_t h0, l0, h1, l1;
            split2(pa[i].x, pa[i].y, h0, l0);
            split2(pa[i].z, pa[i].w, h1, l1);
            sb[off] = h0; sb[off + 1] = h1;
            sb[GOP + off] = l0; sb[GOP + off + 1] = l1;
            split2(pb[i].x, pb[i].y, h0, l0);
            split2(pb[i].z, pb[i].w, h1, l1);
            sb[2 * GOP + off] = h0; sb[2 * GOP + off + 1] = h1;
            sb[3 * GOP + off] = l0; sb[3 * GOP + off + 1] = l1;
        }
    };

    load_regs(0);
    store_stage(sw);
    __syncthreads();

    for (int it = 0; it < NIT; it++) {
        if (it + 1 < NIT) load_regs((it + 1) * 32);
        uint32_t* sb = sw + (it & 1) * GSTGW;
#pragma unroll
        for (int ks = 0; ks < 2; ks++) {
            uint32_t a[4][4], bh[4][2], bl[4][2];
#pragma unroll
            for (int mt = 0; mt < 4; mt++) {
                const uint32_t* p = sb + (warpm * 64 + mt * 16 + gid) * GW + ks * 8 + tg;
                a[mt][0] = p[0]; a[mt][1] = p[8 * GW]; a[mt][2] = p[4]; a[mt][3] = p[8 * GW + 4];
            }
#pragma unroll
            for (int nt = 0; nt < 4; nt++) {
                const uint32_t* p = sb + 2 * GOP + (warpn * 32 + nt * 8 + gid) * GW + ks * 8 + tg;
                bh[nt][0] = p[0]; bh[nt][1] = p[4];
                bl[nt][0] = p[GOP]; bl[nt][1] = p[GOP + 4];
            }
#pragma unroll
            for (int mt = 0; mt < 4; mt++)
#pragma unroll
                for (int nt = 0; nt < 4; nt++) mma_bf16(acc[mt][nt], a[mt], bh[nt]);
#pragma unroll
            for (int mt = 0; mt < 4; mt++)
#pragma unroll
                for (int nt = 0; nt < 4; nt++) mma_bf16(acc[mt][nt], a[mt], bl[nt]);
#pragma unroll
            for (int mt = 0; mt < 4; mt++) {
                const uint32_t* p = sb + GOP + (warpm * 64 + mt * 16 + gid) * GW + ks * 8 + tg;
                a[mt][0] = p[0]; a[mt][1] = p[8 * GW]; a[mt][2] = p[4]; a[mt][3] = p[8 * GW + 4];
            }
#pragma unroll
            for (int mt = 0; mt < 4; mt++)
#pragma unroll
                for (int nt = 0; nt < 4; nt++) mma_bf16(acc[mt][nt], a[mt], bh[nt]);
        }
        if (it + 1 < NIT) store_stage(sw + ((it + 1) & 1) * GSTGW);
        __syncthreads();
    }

#pragma unroll
    for (int mt = 0; mt < 4; mt++) {
#pragma unroll
        for (int nt = 0; nt < 4; nt++) {
            int row = m0 + warpm * 64 + mt * 16 + gid;
            int col = n0 + warpn * 32 + nt * 8 + tg * 2;
            *reinterpret_cast<float2*>(&C[(size_t)row * N + col]) =
                make_float2(acc[mt][nt][0], acc[mt][nt][1]);
            *reinterpret_cast<float2*>(&C[(size_t)(row + 8) * N + col]) =
                make_float2(acc[mt][nt][2], acc[mt][nt][3]);
        }
    }
}

// ---------------- RoPE + RMSNorm + scatter -----------------------------------
__global__ void __launch_bounds__(128) rope_norm_kernel(
    const float* __restrict__ qkv, const float* __restrict__ qw,
    const float* __restrict__ kw, const float* __restrict__ cosf,
    const float* __restrict__ sinf,
    float* __restrict__ Q, float* __restrict__ K, float* __restrict__ V) {
    int bt = blockIdx.x;
    int slot = blockIdx.y;
    int d = threadIdx.x;
    int b = bt / Tt, t = bt % Tt;
    float v = qkv[(size_t)bt * QKV_OUT + slot * HD + d];
    if (slot >= 20) {
        int kh = slot - 20;
        V[(((size_t)(b * KVH + kh)) * Tt + t) * HD + d] = v;
        return;
    }
    float partner = __shfl_xor_sync(0xffffffffu, v, 1);
    int i = d >> 1;
    float c = cosf[t * (HD / 2) + i];
    float s = sinf[t * (HD / 2) + i];
    float o = ((d & 1) == 0) ? (v * c - partner * s) : (partner * s + v * c);
    __shared__ float red[4];
    float ss = o * o;
#pragma unroll
    for (int off = 16; off > 0; off >>= 1) ss += __shfl_xor_sync(0xffffffffu, ss, off);
    if ((d & 31) == 0) red[d >> 5] = ss;
    __syncthreads();
    float tot = red[0] + red[1] + red[2] + red[3];
    float r = rsqrtf(tot * (1.0f / HD) + 1e-6f);
    if (slot < 16) {
        Q[(((size_t)(b * NH + slot)) * Tt + t) * HD + d] = qw[d] * o * r;
    } else {
        int kh = slot - 16;
        K[(((size_t)(b * KVH + kh)) * Tt + t) * HD + d] = kw[d] * o * r;
    }
}

// ---------------- causal flash attention (bf16x3 mma) ------------------------
// smem word layout offsets
#define QW_ 68                       // Q/K word stride (136 bf16)
#define OFF_QHI 0
#define OFF_QLO (OFF_QHI + 64 * QW_)      // 4352
#define OFF_KHI (OFF_QLO + 64 * QW_)      // 8704
#define OFF_KLO (OFF_KHI + 64 * QW_)      // 13056
#define OFF_SF  (OFF_KLO + 64 * QW_)      // 17408, fp32 S [64][68]
#define OFF_VST (OFF_SF + 64 * 68)        // 21760, fp32 V stage [64][133]
#define VSW_ 133
#define OFF_VTH (OFF_VST + 64 * VSW_)     // 30272, Vt hi [128][36]
#define VTW_ 36
#define OFF_VTL (OFF_VTH + 128 * VTW_)    // 34880
#define OFF_PHI (OFF_VTL + 128 * VTW_)    // 39488, P hi [64][36]
#define PW_ 36
#define OFF_PLO (OFF_PHI + 64 * PW_)      // 41792
#define OFF_ST  (OFF_PLO + 64 * PW_)      // 44096: m_s, l_s, rsc (64 each)
#define ATTN_WORDS (OFF_ST + 192)         // 44288 words = 177152 B

__global__ void __launch_bounds__(256, 1) attn_kernel(
    const float* __restrict__ Q, const float* __restrict__ K,
    const float* __restrict__ V, float* __restrict__ Y) {
    extern __shared__ __align__(16) uint32_t sw[];
    float* Sf  = reinterpret_cast<float*>(sw + OFF_SF);
    float* Vst = reinterpret_cast<float*>(sw + OFF_VST);
    float* m_s = reinterpret_cast<float*>(sw + OFF_ST);
    float* l_s = m_s + 64;
    float* rsc = l_s + 64;
    __nv_bfloat16* Phi = reinterpret_cast<__nv_bfloat16*>(sw + OFF_PHI);
    __nv_bfloat16* Plo = reinterpret_cast<__nv_bfloat16*>(sw + OFF_PLO);

    const int tid = threadIdx.x;
    const int warp = tid >> 5, lane = tid & 31;
    const int gid = lane >> 2, tg = lane & 3;
    const int qt = blockIdx.x, h = blockIdx.y, b = blockIdx.z;
    const int kvh = h / (NH / KVH);

    const float* Qg = Q + (((size_t)(b * NH + h)) * Tt + qt * BQ) * HD;
    const float* Kg = K + ((size_t)(b * KVH + kvh)) * Tt * HD;
    const float* Vg = V + ((size_t)(b * KVH + kvh)) * Tt * HD;
    const float scale = 0.08838834764831845f;   // 1/sqrt(128)

    // load Q tile: scale + split into QHI/QLO
#pragma unroll
    for (int i = 0; i < 8; i++) {
        int idx = tid + i * 256;           // 2048 float4s
        int row = idx >> 5, c4 = idx & 31;
        float4 v4 = *reinterpret_cast<const float4*>(&Qg[row * HD + c4 * 4]);
        v4.x *= scale; v4.y *= scale; v4.z *= scale; v4.w *= scale;
        uint32_t h0, l0, h1, l1;
        split2(v4.x, v4.y, h0, l0);
        split2(v4.z, v4.w, h1, l1);
        int off = row * QW_ + c4 * 2;
        sw[OFF_QHI + off] = h0; sw[OFF_QHI + off + 1] = h1;
        sw[OFF_QLO + off] = l0; sw[OFF_QLO + off + 1] = l1;
    }
    if (tid < BQ) { m_s[tid] = -3.0e38f; l_s[tid] = 0.f; }

    float oacc[4][2][4];
#pragma unroll
    for (int i = 0; i < 4; i++)
#pragma unroll
        for (int j = 0; j < 2; j++)
#pragma unroll
            for (int r = 0; r < 4; r++) oacc[i][j][r] = 0.f;

    const int ntiles = qt + 1;
    for (int kt = 0; kt < ntiles; kt++) {
        const int kv0 = kt * BKV;
        __syncthreads();           // all PV of prev iter done before K/Vst overwrite
        // load K (split) and V (fp32 stage)
#pragma unroll
        for (int i = 0; i < 8; i++) {
            int idx = tid + i * 256;
            int row = idx >> 5, c4 = idx & 31;
            float4 kv4 = *reinterpret_cast<const float4*>(&Kg[(size_t)(kv0 + row) * HD + c4 * 4]);
            uint32_t h0, l0, h1, l1;
            split2(kv4.x, kv4.y, h0, l0);
            split2(kv4.z, kv4.w, h1, l1);
            int off = row * QW_ + c4 * 2;
            sw[OFF_KHI + off] = h0; sw[OFF_KHI + off + 1] = h1;
            sw[OFF_KLO + off] = l0; sw[OFF_KLO + off + 1] = l1;
            float4 vv4 = *reinterpret_cast<const float4*>(&Vg[(size_t)(kv0 + row) * HD + c4 * 4]);
            float* vd = &Vst[row * VSW_ + c4 * 4];
            vd[0] = vv4.x; vd[1] = vv4.y; vd[2] = vv4.z; vd[3] = vv4.w;
        }
        __syncthreads();
        // transpose V: Vst[t][d] -> Vt[d][t] (hi/lo bf16, t-pairs packed)
#pragma unroll
        for (int i = 0; i < 16; i++) {
            int idx = tid + i * 256;      // 4096 = 128 d x 32 t-pairs
            int d = idx & 127, tp = idx >> 7;
            float v0 = Vst[(2 * tp) * VSW_ + d];
            float v1 = Vst[(2 * tp + 1) * VSW_ + d];
            uint32_t hi, lo;
            split2(v0, v1, hi, lo);
            sw[OFF_VTH + d * VTW_ + tp] = hi;
            sw[OFF_VTL + d * VTW_ + tp] = lo;
        }
        // S = Q*K^T: warp owns S cols [warp*8, warp*8+8)
        {
            float sacc[4][4];
#pragma unroll
            for (int mt = 0; mt < 4; mt++)
#pragma unroll
                for (int r = 0; r < 4; r++) sacc[mt][r] = 0.f;
            const int rb = warp * 8 + gid;
#pragma unroll
            for (int ks = 0; ks < 8; ks++) {
                uint32_t a[4][4], bh[2], bl[2];
#pragma unroll
                for (int mt = 0; mt < 4; mt++) {
                    const uint32_t* p = sw + OFF_QHI + (mt * 16 + gid) * QW_ + ks * 8 + tg;
                    a[mt][0] = p[0]; a[mt][1] = p[8 * QW_]; a[mt][2] = p[4]; a[mt][3] = p[8 * QW_ + 4];
                }
                const uint32_t* pb = sw + OFF_KHI + rb * QW_ + ks * 8 + tg;
                bh[0] = pb[0]; bh[1] = pb[4];
                const uint32_t* pl = sw + OFF_KLO + rb * QW_ + ks * 8 + tg;
                bl[0] = pl[0]; bl[1] = pl[4];
#pragma unroll
                for (int mt = 0; mt < 4; mt++) mma_bf16(sacc[mt], a[mt], bh);
#pragma unroll
                for (int mt = 0; mt < 4; mt++) mma_bf16(sacc[mt], a[mt], bl);
#pragma unroll
                for (int mt = 0; mt < 4; mt++) {
                    const uint32_t* p = sw + OFF_QLO + (mt * 16 + gid) * QW_ + ks * 8 + tg;
                    a[mt][0] = p[0]; a[mt][1] = p[8 * QW_]; a[mt][2] = p[4]; a[mt][3] = p[8 * QW_ + 4];
                }
#pragma unroll
                for (int mt = 0; mt < 4; mt++) mma_bf16(sacc[mt], a[mt], bh);
            }
#pragma unroll
            for (int mt = 0; mt < 4; mt++) {
                int row = mt * 16 + gid;
                int col = warp * 8 + tg * 2;
                *reinterpret_cast<float2*>(&Sf[row * 68 + col]) =
                    make_float2(sacc[mt][0], sacc[mt][1]);
                *reinterpret_cast<float2*>(&Sf[(row + 8) * 68 + col]) =
                    make_float2(sacc[mt][2], sacc[mt][3]);
            }
        }
        __syncthreads();
        // softmax (4 lanes per row), write P hi/lo bf16
        {
            int row = tid >> 2, g = tid & 3;
            int qglob = qt * BQ + row;
            int jmax = qglob - kv0 + 1;
            if (jmax > BKV) jmax = BKV;
            float mold = m_s[row];
            float mx = mold;
#pragma unroll
            for (int i = 0; i < 16; i++) {
                int j = g + i * 4;
                if (j < jmax) mx = fmaxf(mx, Sf[row * 68 + j]);
            }
            mx = fmaxf(mx, __shfl_xor_sync(0xffffffffu, mx, 1));
            mx = fmaxf(mx, __shfl_xor_sync(0xffffffffu, mx, 2));
            float sum = 0.f;
#pragma unroll
            for (int i = 0; i < 16; i++) {
                int j = g + i * 4;
                float p = (j < jmax) ? __expf(Sf[row * 68 + j] - mx) : 0.f;
                __nv_bfloat16 ph = __float2bfloat16(p);
                Phi[row * (2 * PW_) + j] = ph;
                Plo[row * (2 * PW_) + j] = __float2bfloat16(p - __bfloat162float(ph));
                sum += p;
            }
            sum += __shfl_xor_sync(0xffffffffu, sum, 1);
            sum += __shfl_xor_sync(0xffffffffu, sum, 2);
            if (g == 0) {
                float r = __expf(mold - mx);
                l_s[row] = l_s[row] * r + sum;
                m_s[row] = mx;
                rsc[row] = r;
            }
        }
        __syncthreads();
        // O = O*r + P*V  (warp owns d cols [warp*16, warp*16+16))
        {
#pragma unroll
            for (int mt = 0; mt < 4; mt++) {
                float r1 = rsc[mt * 16 + gid];
                float r2 = rsc[mt * 16 + gid + 8];
#pragma unroll
                for (int nt = 0; nt < 2; nt++) {
                    oacc[mt][nt][0] *= r1; oacc[mt][nt][1] *= r1;
                    oacc[mt][nt][2] *= r2; oacc[mt][nt][3] *= r2;
                }
            }
#pragma unroll
            for (int ks = 0; ks < 4; ks++) {
                uint32_t a[4][4], bh[2][2], bl[2][2];
#pragma unroll
                for (int mt = 0; mt < 4; mt++) {
                    const uint32_t* p = sw + OFF_PHI + (mt * 16 + gid) * PW_ + ks * 8 + tg;
                    a[mt][0] = p[0]; a[mt][1] = p[8 * PW_]; a[mt][2] = p[4]; a[mt][3] = p[8 * PW_ + 4];
                }
#pragma unroll
                for (int nt = 0; nt < 2; nt++) {
                    int drow = warp * 16 + nt * 8 + gid;
                    const uint32_t* p = sw + OFF_VTH + drow * VTW_ + ks * 8 + tg;
                    bh[nt][0] = p[0]; bh[nt][1] = p[4];
                    const uint32_t* pl = sw + OFF_VTL + drow * VTW_ + ks * 8 + tg;
                    bl[nt][0] = pl[0]; bl[nt][1] = pl[4];
                }
#pragma unroll
                for (int mt = 0; mt < 4; mt++)
#pragma unroll
                    for (int nt = 0; nt < 2; nt++) mma_bf16(oacc[mt][nt], a[mt], bh[nt]);
#pragma unroll
                for (int mt = 0; mt < 4; mt++)
#pragma unroll
                    for (int nt = 0; nt < 2; nt++) mma_bf16(oacc[mt][nt], a[mt], bl[nt]);
#pragma unroll
                for (int mt = 0; mt < 4; mt++) {
                    const uint32_t* p = sw + OFF_PLO + (mt * 16 + gid) * PW_ + ks * 8 + tg;
                    a[mt][0] = p[0]; a[mt][1] = p[8 * PW_]; a[mt][2] = p[4]; a[mt][3] = p[8 * PW_ + 4];
                }
#pragma unroll
                for (int mt = 0; mt < 4; mt++)
#pragma unroll
                    for (int nt = 0; nt < 2; nt++) mma_bf16(oacc[mt][nt], a[mt], bh[nt]);
            }
        }
    }

    // epilogue: normalize, write Y
#pragma unroll
    for (int mt = 0; mt < 4; mt++) {
        int row0 = mt * 16 + gid;
        float il0 = 1.0f / l_s[row0];
        float il1 = 1.0f / l_s[row0 + 8];
#pragma unroll
        for (int nt = 0; nt < 2; nt++) {
            int col = h * HD + warp * 16 + nt * 8 + tg * 2;
            size_t r0 = ((size_t)(b * Tt) + qt * BQ + row0) * Cc + col;
            size_t r1 = ((size_t)(b * Tt) + qt * BQ + row0 + 8) * Cc + col;
            *reinterpret_cast<float2*>(&Y[r0]) =
                make_float2(oacc[mt][nt][0] * il0, oacc[mt][nt][1] * il0);
            *reinterpret_cast<float2*>(&Y[r1]) =
                make_float2(oacc[mt][nt][2] * il1, oacc[mt][nt][3] * il1);
        }
    }
}

// ---------------- host launcher ---------------------------------------------
extern "C" void kernel_launch(void* const* d_in, const int* in_sizes, int n_in,
                              void* d_out, int out_size) {
    const float* x      = (const float*)d_in[0];
    const float* w_qkv  = (const float*)d_in[1];
    const float* w_proj = (const float*)d_in[2];
    const float* qw     = (const float*)d_in[3];
    const float* kw     = (const float*)d_in[4];
    const float* fc     = (const float*)d_in[5];
    const float* fs     = (const float*)d_in[6];
    float* out = (float*)d_out;

    float *qkv, *Q, *K, *V, *Y;
    cudaGetSymbolAddress((void**)&qkv, g_qkv);
    cudaGetSymbolAddress((void**)&Q, g_q);
    cudaGetSymbolAddress((void**)&K, g_k);
    cudaGetSymbolAddress((void**)&V, g_v);
    cudaGetSymbolAddress((void**)&Y, g_y);

    const int gemm_smem = 2 * GSTGW * 4;    // 81920 B
    cudaFuncSetAttribute(gemm_bf3, cudaFuncAttributeMaxDynamicSharedMemorySize, gemm_smem);

    const int attn_smem = ATTN_WORDS * 4;   // 177152 B
    cudaFuncSetAttribute(attn_kernel, cudaFuncAttributeMaxDynamicSharedMemorySize, attn_smem);

    // 1) QKV GEMM (bf16x3): [4096,2048] x [3072,2048]^T
    gemm_bf3<<<dim3(QKV_OUT / 128, MROWS / 128), 256, gemm_smem>>>(x, w_qkv, qkv, Cc, QKV_OUT);
    // 2) RoPE + RMSNorm + head scatter
    rope_norm_kernel<<<dim3(MROWS, NH + 2 * KVH), 128>>>(qkv, qw, kw, fc, fs, Q, K, V);
    // 3) causal flash attention (bf16x3)
    attn_kernel<<<dim3(Tt / BQ, NH, Bc), 256, attn_smem>>>(Q, K, V, Y);
    // 4) output projection (bf16x3): [4096,2048] x [2048,2048]^T
    gemm_bf3<<<dim3(Cc / 128, MROWS / 128), 256, gemm_smem>>>(Y, w_proj, out, Cc, Cc);
}

// round 6
// speedup vs baseline: 2.6912x; 1.1688x over previous
#include <cuda_runtime.h>
#include <cuda_bf16.h>
#include <cstdint>

#define Bc 2
#define Tt 2048
#define Cc 2048
#define NH 16
#define KVH 4
#define HD 128
#define QKV_OUT 3072
#define MROWS 4096   // B*T

#define BQ 64
#define BKV 64

typedef __nv_bfloat16 bf16;

// ---------------- scratch ----------------------------------------------------
__device__ float g_qkv[(size_t)MROWS * QKV_OUT];
__device__ bf16 g_xhi[(size_t)MROWS * Cc];
__device__ bf16 g_xlo[(size_t)MROWS * Cc];
__device__ bf16 g_wqkvhi[(size_t)QKV_OUT * Cc];
__device__ bf16 g_wqkvlo[(size_t)QKV_OUT * Cc];
__device__ bf16 g_wprojhi[(size_t)Cc * Cc];
__device__ bf16 g_wprojlo[(size_t)Cc * Cc];
__device__ bf16 g_Qhi[(size_t)Bc * NH * Tt * HD];
__device__ bf16 g_Qlo[(size_t)Bc * NH * Tt * HD];
__device__ bf16 g_Khi[(size_t)Bc * KVH * Tt * HD];
__device__ bf16 g_Klo[(size_t)Bc * KVH * Tt * HD];
__device__ bf16 g_Vthi[(size_t)Bc * KVH * HD * Tt];   // transposed [d][t]
__device__ bf16 g_Vtlo[(size_t)Bc * KVH * HD * Tt];
__device__ bf16 g_Yhi[(size_t)MROWS * Cc];
__device__ bf16 g_Ylo[(size_t)MROWS * Cc];

// ---------------- helpers ----------------------------------------------------
__device__ __forceinline__ uint32_t smem_u32(const void* p) {
    uint32_t a;
    asm("{ .reg .u64 t; cvta.to.shared.u64 t, %1; cvt.u32.u64 %0, t; }" : "=r"(a) : "l"(p));
    return a;
}
__device__ __forceinline__ void cp_async16(uint32_t saddr, const void* g) {
    asm volatile("cp.async.cg.shared.global [%0], [%1], 16;" :: "r"(saddr), "l"(g));
}
#define CP_COMMIT() asm volatile("cp.async.commit_group;" ::: "memory")
#define CP_WAIT0()  asm volatile("cp.async.wait_group 0;" ::: "memory")
#define CP_WAIT1()  asm volatile("cp.async.wait_group 1;" ::: "memory")

__device__ __forceinline__ void mma_bf16(float* d, const uint32_t* a, const uint32_t* b) {
    asm volatile(
        "mma.sync.aligned.m16n8k16.row.col.f32.bf16.bf16.f32 "
        "{%0,%1,%2,%3}, {%4,%5,%6,%7}, {%8,%9}, {%0,%1,%2,%3};"
        : "+f"(d[0]), "+f"(d[1]), "+f"(d[2]), "+f"(d[3])
        : "r"(a[0]), "r"(a[1]), "r"(a[2]), "r"(a[3]), "r"(b[0]), "r"(b[1]));
}

__device__ __forceinline__ void split2(float x, float y, uint32_t& hi, uint32_t& lo) {
    bf16 hx = __float2bfloat16(x);
    bf16 hy = __float2bfloat16(y);
    bf16 lx = __float2bfloat16(x - __bfloat162float(hx));
    bf16 ly = __float2bfloat16(y - __bfloat162float(hy));
    hi = (uint32_t)__bfloat16_as_ushort(hx) | ((uint32_t)__bfloat16_as_ushort(hy) << 16);
    lo = (uint32_t)__bfloat16_as_ushort(lx) | ((uint32_t)__bfloat16_as_ushort(ly) << 16);
}

// ---------------- split fp32 -> bf16 hi/lo -----------------------------------
__global__ void __launch_bounds__(256) split_kernel(const float* __restrict__ src,
                                                    bf16* __restrict__ hi,
                                                    bf16* __restrict__ lo, int n4) {
    int i = blockIdx.x * 256 + threadIdx.x;
    if (i >= n4) return;
    float4 v = reinterpret_cast<const float4*>(src)[i];
    uint32_t h0, l0, h1, l1;
    split2(v.x, v.y, h0, l0);
    split2(v.z, v.w, h1, l1);
    reinterpret_cast<uint2*>(hi)[i] = make_uint2(h0, h1);
    reinterpret_cast<uint2*>(lo)[i] = make_uint2(l0, l1);
}

// ======================= bf16x3 GEMM (pre-split operands) ====================
// C[M,N] = A[M,K] * B[N,K]^T.  CTA 128x128, BK=32, 8 warps @ 64x32, 3 stages.
#define GW 20                 // words per smem row (16 data + 4 pad)
#define GOP (128 * GW)        // words per operand part (2560)
#define GSTGW (4 * GOP)       // words per stage (10240 w = 40 KB)
#define GNST 3

__global__ void __launch_bounds__(256, 1) gemm_bf3(const bf16* __restrict__ Ahi,
                                                   const bf16* __restrict__ Alo,
                                                   const bf16* __restrict__ Bhi,
                                                   const bf16* __restrict__ Blo,
                                                   float* __restrict__ C,
                                                   int K, int N) {
    extern __shared__ __align__(16) uint32_t sw[];
    const int tid = threadIdx.x;
    const int warp = tid >> 5, lane = tid & 31;
    const int gid = lane >> 2, tg = lane & 3;
    const int warpm = warp >> 2, warpn = warp & 3;
    const int m0 = blockIdx.y * 128, n0 = blockIdx.x * 128;
    const int NIT = K / 32;
    const uint32_t sbase = smem_u32(sw);
    const int lr = tid >> 2, lc = tid & 3;    // 512 chunks per part / 256 thr = 2 rows ea

    auto load_stage = [&](int s, int kk) {
        const bf16* srcs[4] = {Ahi + (size_t)m0 * K + kk, Alo + (size_t)m0 * K + kk,
                               Bhi + (size_t)n0 * K + kk, Blo + (size_t)n0 * K + kk};
#pragma unroll
        for (int i = 0; i < 8; i++) {
            int idx = tid + i * 256;              // 2048 chunks
            int part = idx >> 9;
            int r = (idx & 511) >> 2, c = idx & 3;
            uint32_t sa = sbase + (uint32_t)(s * GSTGW + part * GOP + r * GW + c * 4) * 4;
            cp_async16(sa, srcs[part] + (size_t)r * K + c * 8);
        }
    };

    float acc[4][4][4];
#pragma unroll
    for (int i = 0; i < 4; i++)
#pragma unroll
        for (int j = 0; j < 4; j++)
#pragma unroll
            for (int r = 0; r < 4; r++) acc[i][j][r] = 0.f;

    load_stage(0, 0); CP_COMMIT();
    load_stage(1, 32); CP_COMMIT();

    for (int it = 0; it < NIT; it++) {
        if (it == NIT - 1) { CP_WAIT0(); } else { CP_WAIT1(); }
        __syncthreads();
        if (it + 2 < NIT) { load_stage((it + 2) % GNST, (it + 2) * 32); CP_COMMIT(); }

        const uint32_t* sb = sw + (it % GNST) * GSTGW;
#pragma unroll
        for (int ks = 0; ks < 2; ks++) {
            uint32_t ah[4][4], al[4][4], bh[4][2], bl[4][2];
#pragma unroll
            for (int mt = 0; mt < 4; mt++) {
                const uint32_t* p = sb + (warpm * 64 + mt * 16 + gid) * GW + ks * 8 + tg;
                ah[mt][0] = p[0]; ah[mt][1] = p[8 * GW]; ah[mt][2] = p[4]; ah[mt][3] = p[8 * GW + 4];
                const uint32_t* q = p + GOP;
                al[mt][0] = q[0]; al[mt][1] = q[8 * GW]; al[mt][2] = q[4]; al[mt][3] = q[8 * GW + 4];
            }
#pragma unroll
            for (int nt = 0; nt < 4; nt++) {
                const uint32_t* p = sb + 2 * GOP + (warpn * 32 + nt * 8 + gid) * GW + ks * 8 + tg;
                bh[nt][0] = p[0]; bh[nt][1] = p[4];
                bl[nt][0] = p[GOP]; bl[nt][1] = p[GOP + 4];
            }
#pragma unroll
            for (int mt = 0; mt < 4; mt++)
#pragma unroll
                for (int nt = 0; nt < 4; nt++) mma_bf16(acc[mt][nt], ah[mt], bh[nt]);
#pragma unroll
            for (int mt = 0; mt < 4; mt++)
#pragma unroll
                for (int nt = 0; nt < 4; nt++) mma_bf16(acc[mt][nt], ah[mt], bl[nt]);
#pragma unroll
            for (int mt = 0; mt < 4; mt++)
#pragma unroll
                for (int nt = 0; nt < 4; nt++) mma_bf16(acc[mt][nt], al[mt], bh[nt]);
        }
        __syncthreads();
    }

#pragma unroll
    for (int mt = 0; mt < 4; mt++) {
#pragma unroll
        for (int nt = 0; nt < 4; nt++) {
            int row = m0 + warpm * 64 + mt * 16 + gid;
            int col = n0 + warpn * 32 + nt * 8 + tg * 2;
            *reinterpret_cast<float2*>(&C[(size_t)row * N + col]) =
                make_float2(acc[mt][nt][0], acc[mt][nt][1]);
            *reinterpret_cast<float2*>(&C[(size_t)(row + 8) * N + col]) =
                make_float2(acc[mt][nt][2], acc[mt][nt][3]);
        }
    }
}

// ---------------- RoPE + RMSNorm + split-scatter -----------------------------
__global__ void __launch_bounds__(128) rope_norm_kernel(
    const float* __restrict__ qkv, const float* __restrict__ qw,
    const float* __restrict__ kw, const float* __restrict__ cosf,
    const float* __restrict__ sinf) {
    int bt = blockIdx.x;
    int slot = blockIdx.y;
    int d = threadIdx.x;
    int b = bt / Tt, t = bt % Tt;
    float v = qkv[(size_t)bt * QKV_OUT + slot * HD + d];
    if (slot >= 20) {                     // V: split + transpose scatter
        int kh = slot - 20;
        size_t idx = ((size_t)((b * KVH + kh) * HD + d)) * Tt + t;
        bf16 h = __float2bfloat16(v);
        g_Vthi[idx] = h;
        g_Vtlo[idx] = __float2bfloat16(v - __bfloat162float(h));
        return;
    }
    float partner = __shfl_xor_sync(0xffffffffu, v, 1);
    int i = d >> 1;
    float c = cosf[t * (HD / 2) + i];
    float s = sinf[t * (HD / 2) + i];
    float o = ((d & 1) == 0) ? (v * c - partner * s) : (partner * s + v * c);
    __shared__ float red[4];
    float ss = o * o;
#pragma unroll
    for (int off = 16; off > 0; off >>= 1) ss += __shfl_xor_sync(0xffffffffu, ss, off);
    if ((d & 31) == 0) red[d >> 5] = ss;
    __syncthreads();
    float tot = red[0] + red[1] + red[2] + red[3];
    float r = rsqrtf(tot * (1.0f / HD) + 1e-6f);
    if (slot < 16) {
        const float scale = 0.08838834764831845f;   // 1/sqrt(128) baked into Q
        float val = qw[d] * o * r * scale;
        size_t idx = (((size_t)(b * NH + slot)) * Tt + t) * HD + d;
        bf16 h = __float2bfloat16(val);
        g_Qhi[idx] = h;
        g_Qlo[idx] = __float2bfloat16(val - __bfloat162float(h));
    } else {
        int kh = slot - 16;
        float val = kw[d] * o * r;
        size_t idx = (((size_t)(b * KVH + kh)) * Tt + t) * HD + d;
        bf16 h = __float2bfloat16(val);
        g_Khi[idx] = h;
        g_Klo[idx] = __float2bfloat16(val - __bfloat162float(h));
    }
}

// ---------------- causal flash attention (bf16x3, pre-split, cp.async) -------
// smem word offsets
#define QW_ 68
#define AOFF_Q   0                       // Qhi 4352 + Qlo 4352
#define AOFF_K   8704                    // 2 bufs x (hi 4352 + lo 4352)
#define AOFF_VT  26112                   // 2 bufs x (hi 4608 + lo 4608); stride 36
#define VTW_ 36
#define AOFF_SF  44544                   // fp32 S [64][68]
#define AOFF_P   48896                   // Phi 2304 + Plo 2304 (stride 36 words)
#define PW_ 36
#define AOFF_ST  53504                   // m_s, l_s, rsc
#define ATTN_WORDS 53696                 // 214784 B

__global__ void __launch_bounds__(256, 1) attn_kernel(float* __restrict__ dummy) {
    extern __shared__ __align__(16) uint32_t sw[];
    float* Sf  = reinterpret_cast<float*>(sw + AOFF_SF);
    float* m_s = reinterpret_cast<float*>(sw + AOFF_ST);
    float* l_s = m_s + 64;
    float* rsc = l_s + 64;
    bf16* Phi = reinterpret_cast<bf16*>(sw + AOFF_P);
    bf16* Plo = reinterpret_cast<bf16*>(sw + AOFF_P + 64 * PW_);

    const int tid = threadIdx.x;
    const int warp = tid >> 5, lane = tid & 31;
    const int gid = lane >> 2, tg = lane & 3;
    const int qt = blockIdx.x, h = blockIdx.y, b = blockIdx.z;
    const int kvh = h / (NH / KVH);
    const uint32_t sbase = smem_u32(sw);

    const bf16* Qhg = g_Qhi + (((size_t)(b * NH + h)) * Tt + qt * BQ) * HD;
    const bf16* Qlg = g_Qlo + (((size_t)(b * NH + h)) * Tt + qt * BQ) * HD;
    const bf16* Khg = g_Khi + ((size_t)(b * KVH + kvh)) * Tt * HD;
    const bf16* Klg = g_Klo + ((size_t)(b * KVH + kvh)) * Tt * HD;
    const bf16* Vthg = g_Vthi + ((size_t)(b * KVH + kvh)) * HD * Tt;
    const bf16* Vtlg = g_Vtlo + ((size_t)(b * KVH + kvh)) * HD * Tt;

    auto load_kv = [&](int buf, int kv0) {
        uint32_t kb = sbase + (uint32_t)(AOFF_K + buf * 8704) * 4;
        uint32_t vb = sbase + (uint32_t)(AOFF_VT + buf * 9216) * 4;
#pragma unroll
        for (int i = 0; i < 8; i++) {          // K: 2048 chunks
            int idx = tid + i * 256;
            int part = idx >> 10;
            int r = (idx & 1023) >> 4, c = idx & 15;
            const bf16* src = part ? Klg : Khg;
            cp_async16(kb + (uint32_t)(part * 4352 + r * QW_ + c * 4) * 4,
                       src + (size_t)(kv0 + r) * HD + c * 8);
        }
#pragma unroll
        for (int i = 0; i < 8; i++) {          // Vt: 2048 chunks
            int idx = tid + i * 256;
            int part = idx >> 10;
            int d = (idx & 1023) >> 3, c = idx & 7;
            const bf16* src = part ? Vtlg : Vthg;
            cp_async16(vb + (uint32_t)(part * 4608 + d * VTW_ + c * 4) * 4,
                       src + (size_t)d * Tt + kv0 + c * 8);
        }
    };

    // Q load (one-time) + first KV tile, one group
#pragma unroll
    for (int i = 0; i < 8; i++) {
        int idx = tid + i * 256;
        int part = idx >> 10;
        int r = (idx & 1023) >> 4, c = idx & 15;
        const bf16* src = part ? Qlg : Qhg;
        cp_async16(sbase + (uint32_t)(AOFF_Q + part * 4352 + r * QW_ + c * 4) * 4,
                   src + (size_t)r * HD + c * 8);
    }
    load_kv(0, 0);
    CP_COMMIT();

    if (tid < BQ) { m_s[tid] = -3.0e38f; l_s[tid] = 0.f; }

    float oacc[4][2][4];
#pragma unroll
    for (int i = 0; i < 4; i++)
#pragma unroll
        for (int j = 0; j < 2; j++)
#pragma unroll
            for (int r = 0; r < 4; r++) oacc[i][j][r] = 0.f;

    const int ntiles = qt + 1;
    for (int kt = 0; kt < ntiles; kt++) {
        const int kv0 = kt * BKV;
        const int buf = kt & 1;
        if (kt + 1 < ntiles) { load_kv(buf ^ 1, kv0 + BKV); CP_COMMIT(); CP_WAIT1(); }
        else { CP_WAIT0(); }
        __syncthreads();

        const uint32_t* Kb = sw + AOFF_K + buf * 8704;
        const uint32_t* Vb = sw + AOFF_VT + buf * 9216;

        // S = Q*K^T: warp owns S cols [warp*8, warp*8+8)
        {
            float sacc[4][4];
#pragma unroll
            for (int mt = 0; mt < 4; mt++)
#pragma unroll
                for (int r = 0; r < 4; r++) sacc[mt][r] = 0.f;
            const int rb = warp * 8 + gid;
#pragma unroll
            for (int ks = 0; ks < 8; ks++) {
                uint32_t a[4][4], bh[2], bl[2];
#pragma unroll
                for (int mt = 0; mt < 4; mt++) {
                    const uint32_t* p = sw + AOFF_Q + (mt * 16 + gid) * QW_ + ks * 8 + tg;
                    a[mt][0] = p[0]; a[mt][1] = p[8 * QW_]; a[mt][2] = p[4]; a[mt][3] = p[8 * QW_ + 4];
                }
                const uint32_t* pb = Kb + rb * QW_ + ks * 8 + tg;
                bh[0] = pb[0]; bh[1] = pb[4];
                bl[0] = pb[4352]; bl[1] = pb[4352 + 4];
#pragma unroll
                for (int mt = 0; mt < 4; mt++) mma_bf16(sacc[mt], a[mt], bh);
#pragma unroll
                for (int mt = 0; mt < 4; mt++) mma_bf16(sacc[mt], a[mt], bl);
#pragma unroll
                for (int mt = 0; mt < 4; mt++) {
                    const uint32_t* p = sw + AOFF_Q + 4352 + (mt * 16 + gid) * QW_ + ks * 8 + tg;
                    a[mt][0] = p[0]; a[mt][1] = p[8 * QW_]; a[mt][2] = p[4]; a[mt][3] = p[8 * QW_ + 4];
                }
#pragma unroll
                for (int mt = 0; mt < 4; mt++) mma_bf16(sacc[mt], a[mt], bh);
            }
#pragma unroll
            for (int mt = 0; mt < 4; mt++) {
                int row = mt * 16 + gid;
                int col = warp * 8 + tg * 2;
                *reinterpret_cast<float2*>(&Sf[row * 68 + col]) =
                    make_float2(sacc[mt][0], sacc[mt][1]);
                *reinterpret_cast<float2*>(&Sf[(row + 8) * 68 + col]) =
                    make_float2(sacc[mt][2], sacc[mt][3]);
            }
        }
        __syncthreads();

        // softmax: 4 lanes per row
        {
            int row = tid >> 2, g = tid & 3;
            int qglob = qt * BQ + row;
            int jmax = qglob - kv0 + 1;
            if (jmax > BKV) jmax = BKV;
            float mold = m_s[row];
            float mx = mold;
#pragma unroll
            for (int i = 0; i < 16; i++) {
                int j = g + i * 4;
                if (j < jmax) mx = fmaxf(mx, Sf[row * 68 + j]);
            }
            mx = fmaxf(mx, __shfl_xor_sync(0xffffffffu, mx, 1));
            mx = fmaxf(mx, __shfl_xor_sync(0xffffffffu, mx, 2));
            float sum = 0.f;
#pragma unroll
            for (int i = 0; i < 16; i++) {
                int j = g + i * 4;
                float p = (j < jmax) ? __expf(Sf[row * 68 + j] - mx) : 0.f;
                bf16 ph = __float2bfloat16(p);
                Phi[row * (2 * PW_) + j] = ph;
                Plo[row * (2 * PW_) + j] = __float2bfloat16(p - __bfloat162float(ph));
                sum += p;
            }
            sum += __shfl_xor_sync(0xffffffffu, sum, 1);
            sum += __shfl_xor_sync(0xffffffffu, sum, 2);
            if (g == 0) {
                float r = __expf(mold - mx);
                l_s[row] = l_s[row] * r + sum;
                m_s[row] = mx;
                rsc[row] = r;
            }
        }
        __syncthreads();

        // O = O*r + P*V  (warp owns d cols [warp*16, warp*16+16))
        {
#pragma unroll
            for (int mt = 0; mt < 4; mt++) {
                float r1 = rsc[mt * 16 + gid];
                float r2 = rsc[mt * 16 + gid + 8];
#pragma unroll
                for (int nt = 0; nt < 2; nt++) {
                    oacc[mt][nt][0] *= r1; oacc[mt][nt][1] *= r1;
                    oacc[mt][nt][2] *= r2; oacc[mt][nt][3] *= r2;
                }
            }
#pragma unroll
            for (int ks = 0; ks < 4; ks++) {
                uint32_t a[4][4], bh[2][2], bl[2][2];
#pragma unroll
                for (int mt = 0; mt < 4; mt++) {
                    const uint32_t* p = sw + AOFF_P + (mt * 16 + gid) * PW_ + ks * 8 + tg;
                    a[mt][0] = p[0]; a[mt][1] = p[8 * PW_]; a[mt][2] = p[4]; a[mt][3] = p[8 * PW_ + 4];
                }
#pragma unroll
                for (int nt = 0; nt < 2; nt++) {
                    int drow = warp * 16 + nt * 8 + gid;
                    const uint32_t* p = Vb + drow * VTW_ + ks * 8 + tg;
                    bh[nt][0] = p[0]; bh[nt][1] = p[4];
                    bl[nt][0] = p[4608]; bl[nt][1] = p[4608 + 4];
                }
#pragma unroll
                for (int mt = 0; mt < 4; mt++)
#pragma unroll
                    for (int nt = 0; nt < 2; nt++) mma_bf16(oacc[mt][nt], a[mt], bh[nt]);
#pragma unroll
                for (int mt = 0; mt < 4; mt++)
#pragma unroll
                    for (int nt = 0; nt < 2; nt++) mma_bf16(oacc[mt][nt], a[mt], bl[nt]);
#pragma unroll
                for (int mt = 0; mt < 4; mt++) {
                    const uint32_t* p = sw + AOFF_P + 2304 + (mt * 16 + gid) * PW_ + ks * 8 + tg;
                    a[mt][0] = p[0]; a[mt][1] = p[8 * PW_]; a[mt][2] = p[4]; a[mt][3] = p[8 * PW_ + 4];
                }
#pragma unroll
                for (int mt = 0; mt < 4; mt++)
#pragma unroll
                    for (int nt = 0; nt < 2; nt++) mma_bf16(oacc[mt][nt], a[mt], bh[nt]);
            }
        }
        __syncthreads();   // buf free before next iteration's cp.async overwrite
    }

    // epilogue: normalize, split, write Yhi/Ylo
#pragma unroll
    for (int mt = 0; mt < 4; mt++) {
        int row0 = mt * 16 + gid;
        float il0 = 1.0f / l_s[row0];
        float il1 = 1.0f / l_s[row0 + 8];
#pragma unroll
        for (int nt = 0; nt < 2; nt++) {
            int col = h * HD + warp * 16 + nt * 8 + tg * 2;
            size_t r0 = ((size_t)(b * Tt) + qt * BQ + row0) * Cc + col;
            size_t r1 = ((size_t)(b * Tt) + qt * BQ + row0 + 8) * Cc + col;
            uint32_t hw, lw;
            split2(oacc[mt][nt][0] * il0, oacc[mt][nt][1] * il0, hw, lw);
            *reinterpret_cast<uint32_t*>(&g_Yhi[r0]) = hw;
            *reinterpret_cast<uint32_t*>(&g_Ylo[r0]) = lw;
            split2(oacc[mt][nt][2] * il1, oacc[mt][nt][3] * il1, hw, lw);
            *reinterpret_cast<uint32_t*>(&g_Yhi[r1]) = hw;
            *reinterpret_cast<uint32_t*>(&g_Ylo[r1]) = lw;
        }
    }
}

// ---------------- host launcher ---------------------------------------------
extern "C" void kernel_launch(void* const* d_in, const int* in_sizes, int n_in,
                              void* d_out, int out_size) {
    const float* x      = (const float*)d_in[0];
    const float* w_qkv  = (const float*)d_in[1];
    const float* w_proj = (const float*)d_in[2];
    const float* qw     = (const float*)d_in[3];
    const float* kw     = (const float*)d_in[4];
    const float* fc     = (const float*)d_in[5];
    const float* fs     = (const float*)d_in[6];
    float* out = (float*)d_out;

    float* qkv;
    cudaGetSymbolAddress((void**)&qkv, g_qkv);
    bf16 *xhi, *xlo, *wqh, *wql, *wph, *wpl, *yhi, *ylo;
    cudaGetSymbolAddress((void**)&xhi, g_xhi);
    cudaGetSymbolAddress((void**)&xlo, g_xlo);
    cudaGetSymbolAddress((void**)&wqh, g_wqkvhi);
    cudaGetSymbolAddress((void**)&wql, g_wqkvlo);
    cudaGetSymbolAddress((void**)&wph, g_wprojhi);
    cudaGetSymbolAddress((void**)&wpl, g_wprojlo);
    cudaGetSymbolAddress((void**)&yhi, g_Yhi);
    cudaGetSymbolAddress((void**)&ylo, g_Ylo);

    const int gemm_smem = GNST * GSTGW * 4;   // 122880 B
    cudaFuncSetAttribute(gemm_bf3, cudaFuncAttributeMaxDynamicSharedMemorySize, gemm_smem);
    const int attn_smem = ATTN_WORDS * 4;     // 214784 B
    cudaFuncSetAttribute(attn_kernel, cudaFuncAttributeMaxDynamicSharedMemorySize, attn_smem);

    // 0) pre-split inputs and weights to bf16 hi/lo
    {
        int n4 = (MROWS * Cc) / 4;
        split_kernel<<<(n4 + 255) / 256, 256>>>(x, xhi, xlo, n4);
        n4 = (QKV_OUT * Cc) / 4;
        split_kernel<<<(n4 + 255) / 256, 256>>>(w_qkv, wqh, wql, n4);
        n4 = (Cc * Cc) / 4;
        split_kernel<<<(n4 + 255) / 256, 256>>>(w_proj, wph, wpl, n4);
    }
    // 1) QKV GEMM
    gemm_bf3<<<dim3(QKV_OUT / 128, MROWS / 128), 256, gemm_smem>>>(
        xhi, xlo, wqh, wql, qkv, Cc, QKV_OUT);
    // 2) RoPE + RMSNorm + split/scatter (V transposed)
    rope_norm_kernel<<<dim3(MROWS, NH + 2 * KVH), 128>>>(qkv, qw, kw, fc, fs);
    // 3) causal flash attention
    attn_kernel<<<dim3(Tt / BQ, NH, Bc), 256, attn_smem>>>(out);
    // 4) output projection
    gemm_bf3<<<dim3(Cc / 128, MROWS / 128), 256, gemm_smem>>>(
        yhi, ylo, wph, wpl, out, Cc, Cc);
}

// round 7
// speedup vs baseline: 3.5032x; 1.3017x over previous
#include <cuda_runtime.h>
#include <cuda_bf16.h>
#include <cstdint>

#define Bc 2
#define Tt 2048
#define Cc 2048
#define NH 16
#define KVH 4
#define HD 128
#define QKV_OUT 3072
#define MROWS 4096   // B*T

#define BQ 128
#define BKV 64

typedef __nv_bfloat16 bf16;

// ---------------- scratch ----------------------------------------------------
__device__ float g_qkv[(size_t)MROWS * QKV_OUT];
__device__ bf16 g_xhi[(size_t)MROWS * Cc];
__device__ bf16 g_xlo[(size_t)MROWS * Cc];
__device__ bf16 g_wqkvhi[(size_t)QKV_OUT * Cc];
__device__ bf16 g_wqkvlo[(size_t)QKV_OUT * Cc];
__device__ bf16 g_wprojhi[(size_t)Cc * Cc];
__device__ bf16 g_wprojlo[(size_t)Cc * Cc];
__device__ bf16 g_Qhi[(size_t)Bc * NH * Tt * HD];
__device__ bf16 g_Qlo[(size_t)Bc * NH * Tt * HD];
__device__ bf16 g_Khi[(size_t)Bc * KVH * Tt * HD];
__device__ bf16 g_Klo[(size_t)Bc * KVH * Tt * HD];
__device__ bf16 g_Vthi[(size_t)Bc * KVH * HD * Tt];   // transposed [d][t]
__device__ bf16 g_Vtlo[(size_t)Bc * KVH * HD * Tt];
__device__ bf16 g_Yhi[(size_t)MROWS * Cc];
__device__ bf16 g_Ylo[(size_t)MROWS * Cc];

// ---------------- helpers ----------------------------------------------------
__device__ __forceinline__ uint32_t smem_u32(const void* p) {
    uint32_t a;
    asm("{ .reg .u64 t; cvta.to.shared.u64 t, %1; cvt.u32.u64 %0, t; }" : "=r"(a) : "l"(p));
    return a;
}
__device__ __forceinline__ void cp_async16(uint32_t saddr, const void* g) {
    asm volatile("cp.async.cg.shared.global [%0], [%1], 16;" :: "r"(saddr), "l"(g));
}
#define CP_COMMIT() asm volatile("cp.async.commit_group;" ::: "memory")
#define CP_WAIT0()  asm volatile("cp.async.wait_group 0;" ::: "memory")

__device__ __forceinline__ void mma_bf16(float* d, const uint32_t* a, const uint32_t* b) {
    asm volatile(
        "mma.sync.aligned.m16n8k16.row.col.f32.bf16.bf16.f32 "
        "{%0,%1,%2,%3}, {%4,%5,%6,%7}, {%8,%9}, {%0,%1,%2,%3};"
        : "+f"(d[0]), "+f"(d[1]), "+f"(d[2]), "+f"(d[3])
        : "r"(a[0]), "r"(a[1]), "r"(a[2]), "r"(a[3]), "r"(b[0]), "r"(b[1]));
}

__device__ __forceinline__ void split2(float x, float y, uint32_t& hi, uint32_t& lo) {
    bf16 hx = __float2bfloat16(x);
    bf16 hy = __float2bfloat16(y);
    bf16 lx = __float2bfloat16(x - __bfloat162float(hx));
    bf16 ly = __float2bfloat16(y - __bfloat162float(hy));
    hi = (uint32_t)__bfloat16_as_ushort(hx) | ((uint32_t)__bfloat16_as_ushort(hy) << 16);
    lo = (uint32_t)__bfloat16_as_ushort(lx) | ((uint32_t)__bfloat16_as_ushort(ly) << 16);
}

// ---------------- split fp32 -> bf16 hi/lo -----------------------------------
__global__ void __launch_bounds__(256) split_kernel(const float* __restrict__ src,
                                                    bf16* __restrict__ hi,
                                                    bf16* __restrict__ lo, int n4) {
    int i = blockIdx.x * 256 + threadIdx.x;
    if (i >= n4) return;
    float4 v = reinterpret_cast<const float4*>(src)[i];
    uint32_t h0, l0, h1, l1;
    split2(v.x, v.y, h0, l0);
    split2(v.z, v.w, h1, l1);
    reinterpret_cast<uint2*>(hi)[i] = make_uint2(h0, h1);
    reinterpret_cast<uint2*>(lo)[i] = make_uint2(l0, l1);
}

// ======================= bf16x3 GEMM =========================================
// C[M,N] = A[M,K]*B[N,K]^T.  CTA 128x128, 4 warps @ 64x64, BK=32, 2-stage.
#define GW 20                 // words per smem row (16 data + 4 pad)
#define GOP (128 * GW)        // 2560 words per operand part
#define GSTGW (4 * GOP)       // 10240 words per stage (40 KB)

__global__ void __launch_bounds__(128, 2) gemm_bf3(const bf16* __restrict__ Ahi,
                                                   const bf16* __restrict__ Alo,
                                                   const bf16* __restrict__ Bhi,
                                                   const bf16* __restrict__ Blo,
                                                   float* __restrict__ C,
                                                   int K, int N) {
    extern __shared__ __align__(16) uint32_t sw[];
    const int tid = threadIdx.x;
    const int warp = tid >> 5, lane = tid & 31;
    const int gid = lane >> 2, tg = lane & 3;
    const int warpm = warp >> 1, warpn = warp & 1;
    const int m0 = blockIdx.y * 128, n0 = blockIdx.x * 128;
    const int NIT = K / 32;
    const uint32_t sbase = smem_u32(sw);

    auto load_stage = [&](int s, int kk) {
#pragma unroll
        for (int i = 0; i < 16; i++) {
            int idx = tid + i * 128;              // 2048 chunks
            int part = idx >> 9;
            int r = (idx & 511) >> 2, c = idx & 3;
            const bf16* src = (part == 0) ? Ahi : (part == 1) ? Alo
                              : (part == 2) ? Bhi : Blo;
            src += (part < 2) ? (size_t)m0 * K : (size_t)n0 * K;
            cp_async16(sbase + (uint32_t)(s * GSTGW + part * GOP + r * GW + c * 4) * 4,
                       src + (size_t)r * K + kk + c * 8);
        }
    };

    float acc[4][8][4];
#pragma unroll
    for (int i = 0; i < 4; i++)
#pragma unroll
        for (int j = 0; j < 8; j++)
#pragma unroll
            for (int r = 0; r < 4; r++) acc[i][j][r] = 0.f;

    load_stage(0, 0); CP_COMMIT();

    for (int it = 0; it < NIT; it++) {
        CP_WAIT0();
        __syncthreads();
        if (it + 1 < NIT) { load_stage((it + 1) & 1, (it + 1) * 32); CP_COMMIT(); }

        const uint32_t* sb = sw + (it & 1) * GSTGW;
#pragma unroll
        for (int ks = 0; ks < 2; ks++) {
            uint32_t ah[4][4], al[4][4];
#pragma unroll
            for (int mt = 0; mt < 4; mt++) {
                const uint32_t* p = sb + (warpm * 64 + mt * 16 + gid) * GW + ks * 8 + tg;
                ah[mt][0] = p[0]; ah[mt][1] = p[8 * GW]; ah[mt][2] = p[4]; ah[mt][3] = p[8 * GW + 4];
                al[mt][0] = p[GOP]; al[mt][1] = p[GOP + 8 * GW];
                al[mt][2] = p[GOP + 4]; al[mt][3] = p[GOP + 8 * GW + 4];
            }
#pragma unroll
            for (int nt = 0; nt < 8; nt++) {
                const uint32_t* p = sb + 2 * GOP + (warpn * 64 + nt * 8 + gid) * GW + ks * 8 + tg;
                uint32_t bh[2] = {p[0], p[4]};
                uint32_t bl[2] = {p[GOP], p[GOP + 4]};
#pragma unroll
                for (int mt = 0; mt < 4; mt++) mma_bf16(acc[mt][nt], ah[mt], bh);
#pragma unroll
                for (int mt = 0; mt < 4; mt++) mma_bf16(acc[mt][nt], al[mt], bh);
#pragma unroll
                for (int mt = 0; mt < 4; mt++) mma_bf16(acc[mt][nt], ah[mt], bl);
            }
        }
    }

#pragma unroll
    for (int mt = 0; mt < 4; mt++) {
#pragma unroll
        for (int nt = 0; nt < 8; nt++) {
            int row = m0 + warpm * 64 + mt * 16 + gid;
            int col = n0 + warpn * 64 + nt * 8 + tg * 2;
            *reinterpret_cast<float2*>(&C[(size_t)row * N + col]) =
                make_float2(acc[mt][nt][0], acc[mt][nt][1]);
            *reinterpret_cast<float2*>(&C[(size_t)(row + 8) * N + col]) =
                make_float2(acc[mt][nt][2], acc[mt][nt][3]);
        }
    }
}

// ---------------- RoPE + RMSNorm + split-scatter -----------------------------
__global__ void __launch_bounds__(128) rope_norm_kernel(
    const float* __restrict__ qkv, const float* __restrict__ qw,
    const float* __restrict__ kw, const float* __restrict__ cosf,
    const float* __restrict__ sinf) {
    int bt = blockIdx.x;
    int slot = blockIdx.y;
    int d = threadIdx.x;
    int b = bt / Tt, t = bt % Tt;
    float v = qkv[(size_t)bt * QKV_OUT + slot * HD + d];
    if (slot >= 20) {                     // V: split + transpose scatter
        int kh = slot - 20;
        size_t idx = ((size_t)((b * KVH + kh) * HD + d)) * Tt + t;
        bf16 h = __float2bfloat16(v);
        g_Vthi[idx] = h;
        g_Vtlo[idx] = __float2bfloat16(v - __bfloat162float(h));
        return;
    }
    float partner = __shfl_xor_sync(0xffffffffu, v, 1);
    int i = d >> 1;
    float c = cosf[t * (HD / 2) + i];
    float s = sinf[t * (HD / 2) + i];
    float o = ((d & 1) == 0) ? (v * c - partner * s) : (partner * s + v * c);
    __shared__ float red[4];
    float ss = o * o;
#pragma unroll
    for (int off = 16; off > 0; off >>= 1) ss += __shfl_xor_sync(0xffffffffu, ss, off);
    if ((d & 31) == 0) red[d >> 5] = ss;
    __syncthreads();
    float tot = red[0] + red[1] + red[2] + red[3];
    float r = rsqrtf(tot * (1.0f / HD) + 1e-6f);
    if (slot < 16) {
        const float scale = 0.08838834764831845f;   // 1/sqrt(128) baked into Q
        float val = qw[d] * o * r * scale;
        size_t idx = (((size_t)(b * NH + slot)) * Tt + t) * HD + d;
        bf16 h = __float2bfloat16(val);
        g_Qhi[idx] = h;
        g_Qlo[idx] = __float2bfloat16(val - __bfloat162float(h));
    } else {
        int kh = slot - 16;
        float val = kw[d] * o * r;
        size_t idx = (((size_t)(b * KVH + kh)) * Tt + t) * HD + d;
        bf16 h = __float2bfloat16(val);
        g_Khi[idx] = h;
        g_Klo[idx] = __float2bfloat16(val - __bfloat162float(h));
    }
}

// ---------------- causal flash attention (bf16x3, register softmax) ----------
// BQ=128, BKV=64, 8 warps; warp w owns S rows [w*16, w*16+16) entirely.
#define AQW 68                            // Q/K word stride
#define AVW 36                            // Vt word stride
#define AOFF_Q 0                          // 2 parts x 128*AQW = 17408
#define AOFF_K (2 * 128 * AQW)            // 2 bufs x 2 parts x 64*AQW = 17408
#define AOFF_V (AOFF_K + 4 * 64 * AQW)    // 2 bufs x 2 parts x 128*AVW = 18432
#define ATTN_WORDS (AOFF_V + 4 * 128 * AVW)   // 53248 w = 212992 B

__global__ void __launch_bounds__(256, 1) attn_kernel(int qt_tiles) {
    extern __shared__ __align__(16) uint32_t sw[];
    const int tid = threadIdx.x;
    const int warp = tid >> 5, lane = tid & 31;
    const int gid = lane >> 2, tg = lane & 3;
    const int qt = (gridDim.x - 1) - blockIdx.x;   // big tiles first
    const int h = blockIdx.y, b = blockIdx.z;
    const int kvh = h / (NH / KVH);
    const uint32_t sbase = smem_u32(sw);

    const bf16* Qhg = g_Qhi + (((size_t)(b * NH + h)) * Tt + qt * BQ) * HD;
    const bf16* Qlg = g_Qlo + (((size_t)(b * NH + h)) * Tt + qt * BQ) * HD;
    const bf16* Khg = g_Khi + ((size_t)(b * KVH + kvh)) * Tt * HD;
    const bf16* Klg = g_Klo + ((size_t)(b * KVH + kvh)) * Tt * HD;
    const bf16* Vthg = g_Vthi + ((size_t)(b * KVH + kvh)) * HD * Tt;
    const bf16* Vtlg = g_Vtlo + ((size_t)(b * KVH + kvh)) * HD * Tt;

    auto load_kv = [&](int buf, int kv0) {
        uint32_t kb = sbase + (uint32_t)(AOFF_K + buf * 2 * 64 * AQW) * 4;
        uint32_t vb = sbase + (uint32_t)(AOFF_V + buf * 2 * 128 * AVW) * 4;
#pragma unroll
        for (int i = 0; i < 8; i++) {          // K: 2048 chunks
            int idx = tid + i * 256;
            int part = idx >> 10;
            int r = (idx & 1023) >> 4, c = idx & 15;
            const bf16* src = part ? Klg : Khg;
            cp_async16(kb + (uint32_t)(part * 64 * AQW + r * AQW + c * 4) * 4,
                       src + (size_t)(kv0 + r) * HD + c * 8);
        }
#pragma unroll
        for (int i = 0; i < 8; i++) {          // Vt: 2048 chunks
            int idx = tid + i * 256;
            int part = idx >> 10;
            int d = (idx & 1023) >> 3, c = idx & 7;
            const bf16* src = part ? Vtlg : Vthg;
            cp_async16(vb + (uint32_t)(part * 128 * AVW + d * AVW + c * 4) * 4,
                       src + (size_t)d * Tt + kv0 + c * 8);
        }
    };

    // Q (one-time) + first KV tile
#pragma unroll
    for (int i = 0; i < 16; i++) {             // Q: 4096 chunks
        int idx = tid + i * 256;
        int part = idx >> 11;
        int r = (idx & 2047) >> 4, c = idx & 15;
        const bf16* src = part ? Qlg : Qhg;
        cp_async16(sbase + (uint32_t)(AOFF_Q + part * 128 * AQW + r * AQW + c * 4) * 4,
                   src + (size_t)r * HD + c * 8);
    }
    load_kv(0, 0);
    CP_COMMIT();

    const int qbase = qt * BQ + warp * 16;
    float m0 = -1e30f, m1 = -1e30f, l0 = 0.f, l1 = 0.f;
    float oacc[16][4];
#pragma unroll
    for (int i = 0; i < 16; i++)
#pragma unroll
        for (int r = 0; r < 4; r++) oacc[i][r] = 0.f;

    const int ntiles = 2 * qt + 2;
    for (int kt = 0; kt < ntiles; kt++) {
        const int kv0 = kt * BKV;
        const int buf = kt & 1;
        CP_WAIT0();
        __syncthreads();
        if (kt + 1 < ntiles) { load_kv(buf ^ 1, kv0 + BKV); CP_COMMIT(); }

        if (kv0 <= qbase + 15) {               // warp has unmasked work
            const uint32_t* Kb = sw + AOFF_K + buf * 2 * 64 * AQW;
            const uint32_t* Vb = sw + AOFF_V + buf * 2 * 128 * AVW;
            // ---- S = Q K^T : 16 x 64 per warp ----
            float sacc[8][4];
#pragma unroll
            for (int nt = 0; nt < 8; nt++)
#pragma unroll
                for (int r = 0; r < 4; r++) sacc[nt][r] = 0.f;
#pragma unroll
            for (int ks = 0; ks < 8; ks++) {
                const uint32_t* p = sw + AOFF_Q + (warp * 16 + gid) * AQW + ks * 8 + tg;
                uint32_t ah[4] = {p[0], p[8 * AQW], p[4], p[8 * AQW + 4]};
                uint32_t al[4] = {p[128 * AQW], p[136 * AQW], p[128 * AQW + 4], p[136 * AQW + 4]};
#pragma unroll
                for (int nt = 0; nt < 8; nt++) {
                    const uint32_t* pb = Kb + (nt * 8 + gid) * AQW + ks * 8 + tg;
                    uint32_t bh[2] = {pb[0], pb[4]};
                    uint32_t bl[2] = {pb[64 * AQW], pb[64 * AQW + 4]};
                    mma_bf16(sacc[nt], ah, bh);
                    mma_bf16(sacc[nt], al, bh);
                    mma_bf16(sacc[nt], ah, bl);
                }
            }
            // ---- causal mask (diag tiles only) ----
            if (kv0 + 63 > qbase) {
#pragma unroll
                for (int nt = 0; nt < 8; nt++) {
                    int col = kv0 + nt * 8 + tg * 2;
                    if (col > qbase + gid)          sacc[nt][0] = -1e30f;
                    if (col + 1 > qbase + gid)      sacc[nt][1] = -1e30f;
                    if (col > qbase + gid + 8)      sacc[nt][2] = -1e30f;
                    if (col + 1 > qbase + gid + 8)  sacc[nt][3] = -1e30f;
                }
            }
            // ---- online softmax (registers + 2 shuffles) ----
            float mx0 = -1e30f, mx1 = -1e30f;
#pragma unroll
            for (int nt = 0; nt < 8; nt++) {
                mx0 = fmaxf(mx0, fmaxf(sacc[nt][0], sacc[nt][1]));
                mx1 = fmaxf(mx1, fmaxf(sacc[nt][2], sacc[nt][3]));
            }
            mx0 = fmaxf(mx0, __shfl_xor_sync(0xffffffffu, mx0, 1));
            mx0 = fmaxf(mx0, __shfl_xor_sync(0xffffffffu, mx0, 2));
            mx1 = fmaxf(mx1, __shfl_xor_sync(0xffffffffu, mx1, 1));
            mx1 = fmaxf(mx1, __shfl_xor_sync(0xffffffffu, mx1, 2));
            float mn0 = fmaxf(m0, mx0), mn1 = fmaxf(m1, mx1);
            float sc0 = __expf(m0 - mn0), sc1 = __expf(m1 - mn1);
            m0 = mn0; m1 = mn1;
            float sum0 = 0.f, sum1 = 0.f;
#pragma unroll
            for (int nt = 0; nt < 8; nt++) {
                sacc[nt][0] = __expf(sacc[nt][0] - mn0);
                sacc[nt][1] = __expf(sacc[nt][1] - mn0);
                sacc[nt][2] = __expf(sacc[nt][2] - mn1);
                sacc[nt][3] = __expf(sacc[nt][3] - mn1);
                sum0 += sacc[nt][0] + sacc[nt][1];
                sum1 += sacc[nt][2] + sacc[nt][3];
            }
            sum0 += __shfl_xor_sync(0xffffffffu, sum0, 1);
            sum0 += __shfl_xor_sync(0xffffffffu, sum0, 2);
            sum1 += __shfl_xor_sync(0xffffffffu, sum1, 1);
            sum1 += __shfl_xor_sync(0xffffffffu, sum1, 2);
            l0 = l0 * sc0 + sum0;
            l1 = l1 * sc1 + sum1;
#pragma unroll
            for (int i = 0; i < 16; i++) {
                oacc[i][0] *= sc0; oacc[i][1] *= sc0;
                oacc[i][2] *= sc1; oacc[i][3] *= sc1;
            }
            // ---- O += P V  (P fragments built in registers) ----
#pragma unroll
            for (int ks = 0; ks < 4; ks++) {
                uint32_t ph[4], pl[4];
                split2(sacc[2 * ks][0],     sacc[2 * ks][1],     ph[0], pl[0]);
                split2(sacc[2 * ks][2],     sacc[2 * ks][3],     ph[1], pl[1]);
                split2(sacc[2 * ks + 1][0], sacc[2 * ks + 1][1], ph[2], pl[2]);
                split2(sacc[2 * ks + 1][2], sacc[2 * ks + 1][3], ph[3], pl[3]);
#pragma unroll
                for (int ntd = 0; ntd < 16; ntd++) {
                    const uint32_t* pv = Vb + (ntd * 8 + gid) * AVW + ks * 8 + tg;
                    uint32_t bh[2] = {pv[0], pv[4]};
                    uint32_t bl[2] = {pv[128 * AVW], pv[128 * AVW + 4]};
                    mma_bf16(oacc[ntd], ph, bh);
                    mma_bf16(oacc[ntd], pl, bh);
                    mma_bf16(oacc[ntd], ph, bl);
                }
            }
        }
    }

    // epilogue: normalize, split, write Yhi/Ylo
    float il0 = 1.0f / l0, il1 = 1.0f / l1;
#pragma unroll
    for (int ntd = 0; ntd < 16; ntd++) {
        int col = h * HD + ntd * 8 + tg * 2;
        size_t r0 = ((size_t)(b * Tt) + qbase + gid) * Cc + col;
        size_t r1 = r0 + 8 * (size_t)Cc;
        uint32_t hw, lw;
        split2(oacc[ntd][0] * il0, oacc[ntd][1] * il0, hw, lw);
        *reinterpret_cast<uint32_t*>(&g_Yhi[r0]) = hw;
        *reinterpret_cast<uint32_t*>(&g_Ylo[r0]) = lw;
        split2(oacc[ntd][2] * il1, oacc[ntd][3] * il1, hw, lw);
        *reinterpret_cast<uint32_t*>(&g_Yhi[r1]) = hw;
        *reinterpret_cast<uint32_t*>(&g_Ylo[r1]) = lw;
    }
}

// ---------------- host launcher ---------------------------------------------
extern "C" void kernel_launch(void* const* d_in, const int* in_sizes, int n_in,
                              void* d_out, int out_size) {
    const float* x      = (const float*)d_in[0];
    const float* w_qkv  = (const float*)d_in[1];
    const float* w_proj = (const float*)d_in[2];
    const float* qw     = (const float*)d_in[3];
    const float* kw     = (const float*)d_in[4];
    const float* fc     = (const float*)d_in[5];
    const float* fs     = (const float*)d_in[6];
    float* out = (float*)d_out;

    float* qkv;
    cudaGetSymbolAddress((void**)&qkv, g_qkv);
    bf16 *xhi, *xlo, *wqh, *wql, *wph, *wpl, *yhi, *ylo;
    cudaGetSymbolAddress((void**)&xhi, g_xhi);
    cudaGetSymbolAddress((void**)&xlo, g_xlo);
    cudaGetSymbolAddress((void**)&wqh, g_wqkvhi);
    cudaGetSymbolAddress((void**)&wql, g_wqkvlo);
    cudaGetSymbolAddress((void**)&wph, g_wprojhi);
    cudaGetSymbolAddress((void**)&wpl, g_wprojlo);
    cudaGetSymbolAddress((void**)&yhi, g_Yhi);
    cudaGetSymbolAddress((void**)&ylo, g_Ylo);

    const int gemm_smem = 2 * GSTGW * 4;      // 81920 B
    cudaFuncSetAttribute(gemm_bf3, cudaFuncAttributeMaxDynamicSharedMemorySize, gemm_smem);
    const int attn_smem = ATTN_WORDS * 4;     // 212992 B
    cudaFuncSetAttribute(attn_kernel, cudaFuncAttributeMaxDynamicSharedMemorySize, attn_smem);

    // 0) pre-split inputs and weights to bf16 hi/lo
    {
        int n4 = (MROWS * Cc) / 4;
        split_kernel<<<(n4 + 255) / 256, 256>>>(x, xhi, xlo, n4);
        n4 = (QKV_OUT * Cc) / 4;
        split_kernel<<<(n4 + 255) / 256, 256>>>(w_qkv, wqh, wql, n4);
        n4 = (Cc * Cc) / 4;
        split_kernel<<<(n4 + 255) / 256, 256>>>(w_proj, wph, wpl, n4);
    }
    // 1) QKV GEMM
    gemm_bf3<<<dim3(QKV_OUT / 128, MROWS / 128), 128, gemm_smem>>>(
        xhi, xlo, wqh, wql, qkv, Cc, QKV_OUT);
    // 2) RoPE + RMSNorm + split/scatter (V transposed)
    rope_norm_kernel<<<dim3(MROWS, NH + 2 * KVH), 128>>>(qkv, qw, kw, fc, fs);
    // 3) causal flash attention
    attn_kernel<<<dim3(Tt / BQ, NH, Bc), 256, attn_smem>>>(Tt / BQ);
    // 4) output projection
    gemm_bf3<<<dim3(Cc / 128, MROWS / 128), 128, gemm_smem>>>(
        yhi, ylo, wph, wpl, out, Cc, Cc);
}